// round 7
// baseline (speedup 1.0000x reference)
#include <cuda_runtime.h>
#include <cuda_bf16.h>
#include <cstdint>

// GaussianKernel: N=32, R=128, F=128
// Gram form: D[i,j] = ||u_i||^2 - 2 u_i.v_j + ||v_j||^2,  u = x1 - mean, v = x2
// out = softmax_j( exp( exp(-D/(2 sigma^2)) ) )
//
// 128 blocks (1/SM), 256 threads. Thread: 4i x 4j register tile.
// warp w owns i-rows {4w..4w+3}; lane owns j in {lane, lane+32, lane+64, lane+96}.
// Outer exp (bounded arg in (0,1]) is a degree-10 polynomial on the FMA pipe,
// halving the epilogue MUFU wall.

#define N_B 32
#define R_DIM 128
#define F_DIM 128
#define TIB 32
#define X2_STRIDE 132   // padded row stride (floats): conflict-free LDS.128

__device__ __forceinline__ unsigned long long f32x2_fma(unsigned long long a, unsigned long long b, unsigned long long c) {
    unsigned long long r;
    asm("fma.rn.f32x2 %0, %1, %2, %3;" : "=l"(r) : "l"(a), "l"(b), "l"(c));
    return r;
}
__device__ __forceinline__ void f32x2_unpack(unsigned long long u, float& lo, float& hi) {
    asm("mov.b64 {%0, %1}, %2;" : "=f"(lo), "=f"(hi) : "l"(u));
}

// exp(x) for x in [0,1]: Taylor degree 10 (Horner). |err| <= 2.8e-8 abs.
__device__ __forceinline__ float exp01(float x) {
    float r = fmaf(2.75573192e-7f, x, 2.75573192e-6f);  // 1/10!, 1/9!
    r = fmaf(r, x, 2.48015873e-5f);                     // 1/8!
    r = fmaf(r, x, 1.98412698e-4f);                     // 1/7!
    r = fmaf(r, x, 1.38888889e-3f);                     // 1/6!
    r = fmaf(r, x, 8.33333333e-3f);                     // 1/5!
    r = fmaf(r, x, 4.16666667e-2f);                     // 1/4!
    r = fmaf(r, x, 1.66666667e-1f);                     // 1/3!
    r = fmaf(r, x, 0.5f);
    r = fmaf(r, x, 1.0f);
    r = fmaf(r, x, 1.0f);
    return r;
}

__global__ void __launch_bounds__(256, 2)
gaussian_gram_poly(const float4* __restrict__ x1,
                   const float4* __restrict__ x2,
                   const float* __restrict__ sigma,
                   const float* __restrict__ mean,
                   float* __restrict__ out) {
    extern __shared__ float smem[];
    float* x2s   = smem;                         // [128][132]  v
    float* x1s   = x2s + R_DIM * X2_STRIDE;      // [32][128]   u = x1 - mean
    float* normu = x1s + TIB * F_DIM;            // [32]

    const int n    = blockIdx.y;
    const int i0   = blockIdx.x * TIB;
    const int t    = threadIdx.x;
    const int lane = t & 31;
    const int warp = t >> 5;                     // 0..7 -> i-rows 4w..4w+3

    const float mn = mean[0];
    const float sg = sigma[0];
    const float inv2s2 = 1.0f / (2.0f * sg * sg);

    // ---- fill v = x2[n] into padded smem (coalesced float4) ----
    const float4* x2g = x2 + (size_t)n * (R_DIM * F_DIM / 4);
    #pragma unroll
    for (int it = 0; it < (R_DIM * F_DIM / 4) / 256; ++it) {
        int idx4 = t + 256 * it;                 // 0..4095
        int row  = idx4 >> 5;
        int c4   = idx4 & 31;
        *(float4*)&x2s[row * X2_STRIDE + c4 * 4] = x2g[idx4];
    }

    // ---- fill u = x1 tile - mean ----
    const float4* x1g = x1 + ((size_t)n * R_DIM + i0) * (F_DIM / 4);
    #pragma unroll
    for (int it = 0; it < (TIB * F_DIM / 4) / 256; ++it) {
        int idx4 = t + 256 * it;                 // 0..1023
        float4 v = x1g[idx4];
        *(float4*)&x1s[idx4 * 4] = make_float4(v.x - mn, v.y - mn, v.z - mn, v.w - mn);
    }
    __syncthreads();

    // ---- normu: thread t -> row r = t>>3, 16-float chunk c = t&7 ----
    {
        int r = t >> 3, c = t & 7;               // 32 rows x 8 chunks
        const ulonglong2* up = (const ulonglong2*)&x1s[r * F_DIM + c * 16];
        unsigned long long accu = 0ull;
        #pragma unroll
        for (int q = 0; q < 4; ++q) {
            ulonglong2 a = up[q];
            accu = f32x2_fma(a.x, a.x, accu);
            accu = f32x2_fma(a.y, a.y, accu);
        }
        float lo, hi; f32x2_unpack(accu, lo, hi);
        float s = lo + hi;
        s += __shfl_xor_sync(0xffffffffu, s, 1);
        s += __shfl_xor_sync(0xffffffffu, s, 2);
        s += __shfl_xor_sync(0xffffffffu, s, 4);
        if ((t & 7) == 0) normu[r] = s;
    }
    __syncthreads();

    // ---- main loop: 4i x 4j register tile, fold ||v_j||^2 in ----
    unsigned long long acc[4][4];                // [i][j] f32x2 dot partials
    #pragma unroll
    for (int r = 0; r < 4; ++r)
        #pragma unroll
        for (int q = 0; q < 4; ++q) acc[r][q] = 0ull;
    unsigned long long accv[4] = {0ull, 0ull, 0ull, 0ull};

    const ulonglong2* brow = (const ulonglong2*)&x2s[lane * X2_STRIDE]; // + q*32 rows
    const float* arow = &x1s[warp * 4 * F_DIM];
    const int bq_stride = 32 * X2_STRIDE / 4;    // ulonglong2 units per 32 rows

    #pragma unroll 4
    for (int f4 = 0; f4 < F_DIM / 4; ++f4) {
        ulonglong2 b[4];
        #pragma unroll
        for (int q = 0; q < 4; ++q) b[q] = brow[q * bq_stride + f4];
        ulonglong2 a[4];
        #pragma unroll
        for (int r = 0; r < 4; ++r) a[r] = *(const ulonglong2*)&arow[r * F_DIM + f4 * 4];

        #pragma unroll
        for (int q = 0; q < 4; ++q) {
            accv[q] = f32x2_fma(b[q].x, b[q].x, accv[q]);
            accv[q] = f32x2_fma(b[q].y, b[q].y, accv[q]);
        }
        #pragma unroll
        for (int r = 0; r < 4; ++r)
            #pragma unroll
            for (int q = 0; q < 4; ++q) {
                acc[r][q] = f32x2_fma(a[r].x, b[q].x, acc[r][q]);
                acc[r][q] = f32x2_fma(a[r].y, b[q].y, acc[r][q]);
            }
    }

    // ---- epilogue: kernel value, poly outer exp, warp-local softmax ----
    float nv[4];
    #pragma unroll
    for (int q = 0; q < 4; ++q) {
        float lo, hi; f32x2_unpack(accv[q], lo, hi);
        nv[q] = lo + hi;
    }
    float nu[4];
    #pragma unroll
    for (int r = 0; r < 4; ++r) nu[r] = normu[warp * 4 + r];

    float* outbase = out + ((size_t)n * R_DIM + i0 + warp * 4) * R_DIM;

    #pragma unroll
    for (int r = 0; r < 4; ++r) {
        float ex[4];
        float s = 0.0f;
        #pragma unroll
        for (int q = 0; q < 4; ++q) {
            float lo, hi; f32x2_unpack(acc[r][q], lo, hi);
            float D = nu[r] + nv[q] - 2.0f * (lo + hi);
            float k = __expf(-D * inv2s2);       // in (0,1]
            ex[q] = exp01(k);                    // poly exp on FMA pipe
            s += ex[q];
        }
        #pragma unroll
        for (int o = 16; o > 0; o >>= 1)
            s += __shfl_xor_sync(0xffffffffu, s, o);
        const float inv = __fdividef(1.0f, s);
        #pragma unroll
        for (int q = 0; q < 4; ++q)
            outbase[r * R_DIM + lane + 32 * q] = ex[q] * inv;
    }
}

extern "C" void kernel_launch(void* const* d_in, const int* in_sizes, int n_in,
                              void* d_out, int out_size) {
    const float4* x1    = (const float4*)d_in[0];
    const float4* x2    = (const float4*)d_in[1];
    const float*  sigma = (const float*)d_in[2];
    const float*  mean  = (const float*)d_in[3];
    float* out = (float*)d_out;

    const int smem_bytes = (R_DIM * X2_STRIDE + TIB * F_DIM + TIB) * (int)sizeof(float);
    cudaFuncSetAttribute(gaussian_gram_poly,
                         cudaFuncAttributeMaxDynamicSharedMemorySize, smem_bytes);

    dim3 grid(R_DIM / TIB, N_B);   // (4, 32) = 128 blocks -> 1 per SM
    dim3 block(256);
    gaussian_gram_poly<<<grid, block, smem_bytes>>>(x1, x2, sigma, mean, out);
}